// round 6
// baseline (speedup 1.0000x reference)
#include <cuda_runtime.h>
#include <cuda_bf16.h>

#define N_SRC_C   100000
#define N_DST_C   50000
#define N_EDGES_C 800000
#define DD        64

// Scratch (device globals; no allocation allowed)
__device__ float g_sums[N_DST_C * DD];
__device__ float g_cnt[N_DST_C];
// W interleaved for the gemm: float index o = kp*128 + q*32 + tx*4 + f
// holds W[8*tx + 2*q + (f>>1)][2*kp + (f&1)]  (kp = k-pair 0..63)
__device__ float g_Wt[128 * 64];

// Packed f32x2 helpers (sm_103a)
#define FMA2(d, a, bb) \
    asm("fma.rn.f32x2 %0, %1, %2, %3;" : "=l"(d) : "l"(a), "l"(bb), "l"(d))
#define MUL2(d, a, bb) \
    asm("mul.rn.f32x2 %0, %1, %2;" : "=l"(d) : "l"(a), "l"(bb))
#define PACKDUP(o, x) \
    asm("mov.b64 %0, {%1, %1};" : "=l"(o) : "f"(x))

// ---------------------------------------------------------------------------
// Kernel 1: zero scratch + interleave W into g_Wt
// ---------------------------------------------------------------------------
__global__ void prep_kernel(const float* __restrict__ W) {
    int i = blockIdx.x * blockDim.x + threadIdx.x;
    int stride = gridDim.x * blockDim.x;
    const int n4 = (N_DST_C * DD) / 4;
    float4 z = make_float4(0.f, 0.f, 0.f, 0.f);
    for (int j = i; j < n4; j += stride)
        reinterpret_cast<float4*>(g_sums)[j] = z;
    for (int j = i; j < N_DST_C; j += stride)
        g_cnt[j] = 0.f;
    for (int o = i; o < 128 * 64; o += stride) {
        int kp = o >> 7, r = o & 127;
        int q  = r >> 5;
        int tx = (r >> 2) & 7;
        int f  = r & 3;
        int j  = 8 * tx + 2 * q + (f >> 1);
        int k  = 2 * kp + (f & 1);
        g_Wt[o] = __ldg(W + j * 128 + k);
    }
}

// ---------------------------------------------------------------------------
// Kernel 2: segmented edge aggregation. 16-thread groups, float4 per thread.
// dst_idx sorted -> register accumulation per segment, atomic flush on change.
// ---------------------------------------------------------------------------
__global__ void __launch_bounds__(256)
agg_kernel(const float* __restrict__ H_src,
           const int*   __restrict__ src_idx,
           const int*   __restrict__ dst_idx) {
    const int EPG = 64;                         // edges per 16-thread group
    int g = blockIdx.x * 16 + (threadIdx.x >> 4);
    if (g >= N_EDGES_C / EPG) return;
    int c4 = threadIdx.x & 15;                  // float4 column index
    int e0 = g * EPG;

    float4 acc = make_float4(0.f, 0.f, 0.f, 0.f);
    float run = 0.f;
    int   cur = -1;

    #pragma unroll 1
    for (int base = e0; base < e0 + EPG; base += 8) {
        int4 s0 = __ldg((const int4*)(src_idx + base));
        int4 s1 = __ldg((const int4*)(src_idx + base + 4));
        int4 d0 = __ldg((const int4*)(dst_idx + base));
        int4 d1 = __ldg((const int4*)(dst_idx + base + 4));
        int s[8] = { s0.x, s0.y, s0.z, s0.w, s1.x, s1.y, s1.z, s1.w };
        int d[8] = { d0.x, d0.y, d0.z, d0.w, d1.x, d1.y, d1.z, d1.w };
        float4 v[8];
        #pragma unroll
        for (int j = 0; j < 8; j++)
            v[j] = __ldg((const float4*)(H_src + (size_t)s[j] * DD) + c4);
        #pragma unroll
        for (int j = 0; j < 8; j++) {
            if (d[j] != cur) {
                if (cur >= 0) {
                    float* p = g_sums + (size_t)cur * DD + c4 * 4;
                    atomicAdd(p + 0, acc.x);
                    atomicAdd(p + 1, acc.y);
                    atomicAdd(p + 2, acc.z);
                    atomicAdd(p + 3, acc.w);
                    if (c4 == 0) atomicAdd(g_cnt + cur, run);
                }
                cur = d[j];
                acc = make_float4(0.f, 0.f, 0.f, 0.f);
                run = 0.f;
            }
            acc.x += v[j].x; acc.y += v[j].y;
            acc.z += v[j].z; acc.w += v[j].w;
            run += 1.f;
        }
    }
    if (cur >= 0) {
        float* p = g_sums + (size_t)cur * DD + c4 * 4;
        atomicAdd(p + 0, acc.x);
        atomicAdd(p + 1, acc.y);
        atomicAdd(p + 2, acc.z);
        atomicAdd(p + 3, acc.w);
        if (c4 == 0) atomicAdd(g_cnt + cur, run);
    }
}

// ---------------------------------------------------------------------------
// Kernel 3 (fused): y = 0.9*HBar + 0.1*sums/max(cnt,1) -> out2,
//                   h = relu([H_dst, y] @ W^T + b)      -> out
// 256 threads, 64 rows x 64 cols per block; 2 rows x 8 cols per thread.
// k-pair packed f32x2: acc2[j] += {x[2k],x[2k+1]} * {W[j][2k],W[j][2k+1]}
// (no PACKDUP on the FMA chain), horizontal add at the end.
// W pre-interleaved so each LDS.128 wavefront is a contiguous 128B row
// (conflict-free).
// ---------------------------------------------------------------------------
__global__ void __launch_bounds__(256)
gemm_kernel(const float* __restrict__ H_dst,
            const float* __restrict__ HBar,
            const float* __restrict__ b,
            float* __restrict__ out,
            float* __restrict__ out2) {
    __shared__ float ws[128 * 64];

    int t = threadIdx.x;
    #pragma unroll
    for (int i = 0; i < 8; i++) {
        int idx = t + i * 256;
        reinterpret_cast<float4*>(ws)[idx] =
            __ldg(reinterpret_cast<const float4*>(g_Wt) + idx);
    }
    __syncthreads();

    int tx = t & 7;
    int ty = t >> 3;
    int j0 = tx * 8;
    int r0 = (blockIdx.x << 6) + ty * 2;

    int row0 = min(r0,     N_DST_C - 1);
    int row1 = min(r0 + 1, N_DST_C - 1);

    unsigned long long acc0[8], acc1[8];
    #pragma unroll
    for (int q = 0; q < 8; q++) { acc0[q] = 0ull; acc1[q] = 0ull; }

    const float* wbase = ws + tx * 4;

    // ---- first half: k = 0..63 over H_dst ----
    {
        const float* x0 = H_dst + (size_t)row0 * DD;
        const float* x1 = H_dst + (size_t)row1 * DD;
        #pragma unroll 4
        for (int k4 = 0; k4 < 64; k4 += 4) {
            float4 a0 = __ldg((const float4*)(x0 + k4));
            float4 a1 = __ldg((const float4*)(x1 + k4));
            const unsigned long long* pa0 = (const unsigned long long*)&a0;
            const unsigned long long* pa1 = (const unsigned long long*)&a1;
            #pragma unroll
            for (int kk = 0; kk < 2; kk++) {
                int kp = (k4 >> 1) + kk;
                unsigned long long xl0 = pa0[kk];
                unsigned long long xl1 = pa1[kk];
                const float* wb = wbase + kp * 128;
                #pragma unroll
                for (int q = 0; q < 4; q++) {
                    ulonglong2 w = *(const ulonglong2*)(wb + q * 32);
                    FMA2(acc0[2*q],     xl0, w.x);
                    FMA2(acc0[2*q + 1], xl0, w.y);
                    FMA2(acc1[2*q],     xl1, w.x);
                    FMA2(acc1[2*q + 1], xl1, w.y);
                }
            }
        }
    }

    // ---- second half: k = 64..127 over y (computed on the fly) ----
    {
        unsigned long long inv0_2, inv1_2, c09;
        PACKDUP(inv0_2, 0.1f / fmaxf(__ldg(g_cnt + row0), 1.f));
        PACKDUP(inv1_2, 0.1f / fmaxf(__ldg(g_cnt + row1), 1.f));
        PACKDUP(c09, 0.9f);

        const float* s0  = g_sums + (size_t)row0 * DD;
        const float* s1  = g_sums + (size_t)row1 * DD;
        const float* hb0 = HBar   + (size_t)row0 * DD;
        const float* hb1 = HBar   + (size_t)row1 * DD;
        float* o20 = out2 + (size_t)row0 * DD;
        float* o21 = out2 + (size_t)row1 * DD;
        bool st0 = (tx == 0) && (r0     < N_DST_C);
        bool st1 = (tx == 0) && (r0 + 1 < N_DST_C);

        #pragma unroll 4
        for (int k4 = 0; k4 < 64; k4 += 4) {
            float4 sv0 = __ldg((const float4*)(s0  + k4));
            float4 sv1 = __ldg((const float4*)(s1  + k4));
            float4 hv0 = __ldg((const float4*)(hb0 + k4));
            float4 hv1 = __ldg((const float4*)(hb1 + k4));
            const unsigned long long* ps0 = (const unsigned long long*)&sv0;
            const unsigned long long* ps1 = (const unsigned long long*)&sv1;
            const unsigned long long* ph0 = (const unsigned long long*)&hv0;
            const unsigned long long* ph1 = (const unsigned long long*)&hv1;

            ulonglong2 y0, y1;
            // y = s*inv; y += 0.9*hb   (packed)
            MUL2(y0.x, ps0[0], inv0_2);  FMA2(y0.x, ph0[0], c09);
            MUL2(y0.y, ps0[1], inv0_2);  FMA2(y0.y, ph0[1], c09);
            MUL2(y1.x, ps1[0], inv1_2);  FMA2(y1.x, ph1[0], c09);
            MUL2(y1.y, ps1[1], inv1_2);  FMA2(y1.y, ph1[1], c09);

            if (st0) *(ulonglong2*)(o20 + k4) = y0;
            if (st1) *(ulonglong2*)(o21 + k4) = y1;

            const unsigned long long ya0[2] = { y0.x, y0.y };
            const unsigned long long ya1[2] = { y1.x, y1.y };
            #pragma unroll
            for (int kk = 0; kk < 2; kk++) {
                int kp = 32 + (k4 >> 1) + kk;
                unsigned long long xl0 = ya0[kk];
                unsigned long long xl1 = ya1[kk];
                const float* wb = wbase + kp * 128;
                #pragma unroll
                for (int q = 0; q < 4; q++) {
                    ulonglong2 w = *(const ulonglong2*)(wb + q * 32);
                    FMA2(acc0[2*q],     xl0, w.x);
                    FMA2(acc0[2*q + 1], xl0, w.y);
                    FMA2(acc1[2*q],     xl1, w.x);
                    FMA2(acc1[2*q + 1], xl1, w.y);
                }
            }
        }
    }

    // ---- epilogue: horizontal add, bias, relu, store ----
    float4 b0 = __ldg((const float4*)(b + j0));
    float4 b1 = __ldg((const float4*)(b + j0 + 4));
    float bb[8] = { b0.x, b0.y, b0.z, b0.w, b1.x, b1.y, b1.z, b1.w };

    float h0[8], h1[8];
    #pragma unroll
    for (int q = 0; q < 8; q++) {
        float2 v0 = *(float2*)&acc0[q];
        float2 v1 = *(float2*)&acc1[q];
        h0[q] = fmaxf(v0.x + v0.y + bb[q], 0.f);
        h1[q] = fmaxf(v1.x + v1.y + bb[q], 0.f);
    }
    if (r0 < N_DST_C) {
        float* p = out + (size_t)r0 * DD + j0;
        *(float4*)(p)     = make_float4(h0[0], h0[1], h0[2], h0[3]);
        *(float4*)(p + 4) = make_float4(h0[4], h0[5], h0[6], h0[7]);
    }
    if (r0 + 1 < N_DST_C) {
        float* p = out + (size_t)(r0 + 1) * DD + j0;
        *(float4*)(p)     = make_float4(h1[0], h1[1], h1[2], h1[3]);
        *(float4*)(p + 4) = make_float4(h1[4], h1[5], h1[6], h1[7]);
    }
}

// ---------------------------------------------------------------------------
// Launch
// ---------------------------------------------------------------------------
extern "C" void kernel_launch(void* const* d_in, const int* in_sizes, int n_in,
                              void* d_out, int out_size) {
    const float* H_src   = (const float*)d_in[0];
    const float* H_dst   = (const float*)d_in[1];
    const float* HBar    = (const float*)d_in[2];
    const int*   src_idx = (const int*)  d_in[3];
    const int*   dst_idx = (const int*)  d_in[4];
    const float* W       = (const float*)d_in[5];
    const float* b       = (const float*)d_in[6];

    float* out  = (float*)d_out;                    // h:       [N_DST, 64]
    float* out2 = out + (size_t)N_DST_C * DD;       // h_neigh: [N_DST, 64]

    prep_kernel<<<256, 256>>>(W);
    agg_kernel<<<(N_EDGES_C / 64 + 15) / 16, 256>>>(H_src, src_idx, dst_idx);
    gemm_kernel<<<(N_DST_C + 63) / 64, 256>>>(H_dst, HBar, b, out, out2);
}